// round 14
// baseline (speedup 1.0000x reference)
#include <cuda_runtime.h>
#include <cuda_fp16.h>
#include <mma.h>
#include <cstdint>

using namespace nvcuda;

#define NN   100000
#define NE   1600000
#define FBLK 592          // 148 SMs x 4 blocks
#define FTHR 512

// ---------------- scratch (device globals; no allocation allowed) ----------
__device__ int    d_flag;                // 1 => edge indices stored as int64
__device__ int    d_deg[NN];             // edge count per dst (memset 0)
__device__ float  d_dinv[NN];            // (cnt+1)^-1/2
__device__ int    d_off[NN + 1];         // CSR offsets (by dst)
__device__ int    d_cur[NN];             // fill cursors
__device__ int    d_bsum[256];           // per-scanblock totals (196 used)
__device__ int    d_sync[4];             // handshake counters (memset 0)
__device__ int    d_srcl[NE];            // CSR src lists
__device__ __half d_xh[(size_t)NN * 128];  // x fp16, later h1 fp16
__device__ __half d_g[(size_t)NN * 128];   // g1 fp16 (128w) / g2 fp16 (64w)
__device__ __half d_z[(size_t)NN * 64];    // z fp16
__device__ __half d_w1h[128 * 128];
__device__ __half d_w2h[128 * 64];

__device__ __forceinline__ int ld_idx(const int* __restrict__ p, long long i, int flag) {
    return flag ? p[2 * i] : p[i];
}

// grid-wide sync: all FBLK blocks co-resident by construction
__device__ __forceinline__ void gsync(int idx) {
    __syncthreads();
    if (threadIdx.x == 0) {
        __threadfence();
        atomicAdd(&d_sync[idx], 1);
        while (*(volatile int*)&d_sync[idx] < FBLK) __nanosleep(64);
    }
    __syncthreads();
}

// ---------------- fused front: convw+detect -> degree -> dinv+scan ------------
__global__ void __launch_bounds__(FTHR, 4)
k_front(const int* __restrict__ p,
        const float* __restrict__ W1, const float* __restrict__ W2) {
    int tid = threadIdx.x, lane = tid & 31, wid = tid >> 5;
    int gtid = blockIdx.x * FTHR + tid;

    // phase A: weight conversion + index-width detect
    for (int i = gtid; i < 128 * 128; i += FBLK * FTHR) {
        d_w1h[i] = __float2half(W1[i]);
        if (i < 128 * 64) d_w2h[i] = __float2half(W2[i]);
    }
    if (blockIdx.x == 0 && tid < 32) {
        int nz = 0;
        for (int j = tid; j < 512; j += 32) nz |= p[2 * j + 1];
        for (int o = 16; o; o >>= 1) nz |= __shfl_down_sync(0xffffffffu, nz, o);
        if (tid == 0) d_flag = (nz == 0) ? 1 : 0;
    }
    gsync(0);

    // phase B: degree atomics (d_deg pre-zeroed by memset)
    int flag = *(volatile int*)&d_flag;
    for (long long e = gtid; e < NE; e += (long long)FBLK * FTHR) {
        int dst = ld_idx(p, NE + e, flag);
        atomicAdd(&d_deg[dst], 1);
    }
    gsync(1);

    // phase C: dinv + exclusive scan of cnt over NN (blocks 0..195 do the work)
    constexpr int NSB = (NN + FTHR - 1) / FTHR;  // 196 scan blocks
    __shared__ int wsum[16];
    __shared__ int sh[224];
    int excl = 0, val = 0;
    if (blockIdx.x < NSB) {
        int v = blockIdx.x * FTHR + tid;
        int cnt = (v < NN) ? *(volatile int*)&d_deg[v] : 0;
        if (v < NN) d_dinv[v] = rsqrtf((float)(cnt + 1));
        val = cnt;
        int x = val;
        #pragma unroll
        for (int o = 1; o < 32; o <<= 1) {
            int t = __shfl_up_sync(0xffffffffu, x, o);
            if (lane >= o) x += t;
        }
        if (lane == 31) wsum[wid] = x;
        __syncthreads();
        if (wid == 0 && lane < 16) {
            int y = wsum[lane];
            #pragma unroll
            for (int o = 1; o < 16; o <<= 1) {
                int t = __shfl_up_sync(0xffffu, y, o);
                if (lane >= o) y += t;
            }
            wsum[lane] = y;
        }
        __syncthreads();
        int warpoff = wid ? wsum[wid - 1] : 0;
        excl = warpoff + x - val;
        if (tid == FTHR - 1) {
            d_bsum[blockIdx.x] = warpoff + x;   // block total
        }
    }
    gsync(2);

    if (blockIdx.x < NSB) {
        // every scan-block prefix-scans the 196 block totals.
        // FIX: pad participation to 224 threads (7 FULL warps) so every
        // ws2[0..6] is written by its warp's lane 31 (R13 left ws2[6]
        // uninitialized -> garbage offsets -> runaway gather loops).
        __shared__ int ws2[7];
        int bx = 0;
        if (tid < 224) {
            bx = (tid < NSB) ? *(volatile int*)&d_bsum[tid] : 0;
            #pragma unroll
            for (int o = 1; o < 32; o <<= 1) {
                int t = __shfl_up_sync(0xffffffffu, bx, o);
                if (lane >= o) bx += t;
            }
            if (lane == 31) ws2[wid] = bx;   // wid in 0..6, all written
        }
        __syncthreads();
        if (tid < NSB) {
            int add2 = 0;
            for (int q = 0; q < wid; q++) add2 += ws2[q];
            sh[tid] = bx + add2;   // inclusive prefix of block totals
        }
        __syncthreads();
        int addb = blockIdx.x ? sh[blockIdx.x - 1] : 0;
        int v = blockIdx.x * FTHR + tid;
        if (v < NN) {
            int o = excl + addb;
            d_off[v] = o;
            d_cur[v] = o;
        }
        if (v == 0) d_off[NN] = NE;   // sum(cnt) == NE exactly
    }
}

// ---------------- x -> fp16 ---------------------------------------------------
__global__ void k_convx(const float* __restrict__ x) {
    long long i = (long long)blockIdx.x * blockDim.x + threadIdx.x;  // 8-half unit
    if (i >= (long long)NN * 128 / 8) return;
    float4 a = *(const float4*)&x[i * 8];
    float4 b = *(const float4*)&x[i * 8 + 4];
    __half2 h[4];
    h[0] = __floats2half2_rn(a.x, a.y);
    h[1] = __floats2half2_rn(a.z, a.w);
    h[2] = __floats2half2_rn(b.x, b.y);
    h[3] = __floats2half2_rn(b.z, b.w);
    *(uint4*)&d_xh[i * 8] = *(uint4*)h;
}

// ---------------- CSR fill ---------------------------------------------------
__global__ void k_fill(const int* __restrict__ p) {
    long long e = (long long)blockIdx.x * blockDim.x + threadIdx.x;
    if (e >= NE) return;
    int flag = d_flag;
    int src = ld_idx(p, e, flag);
    int dst = ld_idx(p, NE + e, flag);
    int pos = atomicAdd(&d_cur[dst], 1);
    d_srcl[pos] = src;
}

// ---------------- wmma GEMM, padded smem ---------------------------------------
// BM=64 rows/block, K=128. BN=128 (8 warps) or BN=64 (4 warps). fp32 acc.
template <int BN>
__global__ void k_gemm_wmma(const __half* __restrict__ A, const __half* __restrict__ Wh,
                            __half* __restrict__ out) {
    constexpr int BM = 64, K = 128;
    constexpr int LDA = K + 8;
    constexpr int LDW = BN + 8;
    constexpr int NWARP = 4 * (BN / 64);
    constexpr int NT = NWARP * 32;
    extern __shared__ __half dyn[];
    __half* sA = dyn;                   // BM * LDA
    __half* sW = dyn + BM * LDA;        // K * LDW

    const int tid = threadIdx.x;
    const int wid = tid >> 5, lane = tid & 31;
    const int wm = wid & 3, wn = wid >> 2;
    const int rowBase = blockIdx.x * BM;

    for (int i = tid; i < BM * K / 8; i += NT) {
        int r = i >> 4;
        int c = (i & 15) * 8;
        int row = min(rowBase + r, NN - 1);
        *(uint4*)&sA[r * LDA + c] = *(const uint4*)&A[(size_t)row * K + c];
    }
    for (int i = tid; i < K * BN / 8; i += NT) {
        int r = i / (BN / 8);
        int c = (i % (BN / 8)) * 8;
        *(uint4*)&sW[r * LDW + c] = *(const uint4*)&Wh[(size_t)r * BN + c];
    }
    __syncthreads();

    wmma::fragment<wmma::accumulator, 16, 16, 16, float> c[4];
    #pragma unroll
    for (int n = 0; n < 4; n++) wmma::fill_fragment(c[n], 0.f);

    #pragma unroll
    for (int k = 0; k < K; k += 16) {
        wmma::fragment<wmma::matrix_a, 16, 16, 16, __half, wmma::row_major> a;
        wmma::load_matrix_sync(a, &sA[(wm * 16) * LDA + k], LDA);
        #pragma unroll
        for (int n = 0; n < 4; n++) {
            wmma::fragment<wmma::matrix_b, 16, 16, 16, __half, wmma::row_major> b;
            wmma::load_matrix_sync(b, &sW[k * LDW + wn * 64 + n * 16], LDW);
            wmma::mma_sync(c[n], a, b, c[n]);
        }
    }
    __syncthreads();  // done with sW; reuse as fp32 staging

    float* stage = (float*)sW + (size_t)wid * 16 * 64;  // 4KB per warp
    #pragma unroll
    for (int n = 0; n < 4; n++)
        wmma::store_matrix_sync(stage + n * 16, c[n], 64, wmma::mem_row_major);
    __syncwarp();

    for (int i = lane; i < 128; i += 32) {
        int r = i >> 3;
        int cc = (i & 7) * 8;
        int row = rowBase + wm * 16 + r;
        if (row < NN) {
            float dv = d_dinv[row];
            __half2 hv[4];
            #pragma unroll
            for (int q = 0; q < 4; q++) {
                float v0 = stage[r * 64 + cc + 2 * q] * dv;
                float v1 = stage[r * 64 + cc + 2 * q + 1] * dv;
                hv[q] = __floats2half2_rn(v0, v1);
            }
            *(uint4*)&out[(size_t)row * BN + wn * 64 + cc] = *(uint4*)hv;
        }
    }
}

// ---------------- layer-1 aggregate: warp per node, 128 cols fp16 ------------
__global__ void k_gather1(const float* __restrict__ b1) {
    int warp = (blockIdx.x * blockDim.x + threadIdx.x) >> 5;
    int lane = threadIdx.x & 31;
    if (warp >= NN) return;
    const uint2* g = (const uint2*)d_g;
    uint2 sv = g[(size_t)warp * 32 + lane];
    float2 f0 = __half22float2(*(__half2*)&sv.x);
    float2 f1 = __half22float2(*(__half2*)&sv.y);
    float4 acc = make_float4(f0.x, f0.y, f1.x, f1.y);  // self-loop term
    int s = d_off[warp], e = d_off[warp + 1];
    for (int i = s; i < e; i += 32) {
        int u = (i + lane < e) ? d_srcl[i + lane] : 0;
        int m = min(32, e - i);
        for (int j = 0; j < m; j++) {
            int uu = __shfl_sync(0xffffffffu, u, j);
            uint2 tv = g[(size_t)uu * 32 + lane];
            float2 t0 = __half22float2(*(__half2*)&tv.x);
            float2 t1 = __half22float2(*(__half2*)&tv.y);
            acc.x += t0.x; acc.y += t0.y; acc.z += t1.x; acc.w += t1.y;
        }
    }
    float dv = d_dinv[warp];
    float4 bb = ((const float4*)b1)[lane];
    __half2 h0 = __floats2half2_rn(fmaxf(dv * acc.x + bb.x, 0.f),
                                   fmaxf(dv * acc.y + bb.y, 0.f));
    __half2 h1 = __floats2half2_rn(fmaxf(dv * acc.z + bb.z, 0.f),
                                   fmaxf(dv * acc.w + bb.w, 0.f));
    uint2 o;
    o.x = *(unsigned*)&h0;
    o.y = *(unsigned*)&h1;
    ((uint2*)d_xh)[(size_t)warp * 32 + lane] = o;  // h1 fp16 over xh
}

// ---------------- layer-2 aggregate: warp per node, 64 cols fp16 -------------
__global__ void k_gather2(const float* __restrict__ b2) {
    int warp = (blockIdx.x * blockDim.x + threadIdx.x) >> 5;
    int lane = threadIdx.x & 31;
    if (warp >= NN) return;
    const unsigned* g = (const unsigned*)d_g;
    float2 acc = __half22float2(*(__half2*)&g[(size_t)warp * 32 + lane]);
    int s = d_off[warp], e = d_off[warp + 1];
    for (int i = s; i < e; i += 32) {
        int u = (i + lane < e) ? d_srcl[i + lane] : 0;
        int m = min(32, e - i);
        for (int j = 0; j < m; j++) {
            int uu = __shfl_sync(0xffffffffu, u, j);
            unsigned tv = g[(size_t)uu * 32 + lane];
            float2 t = __half22float2(*(__half2*)&tv);
            acc.x += t.x; acc.y += t.y;
        }
    }
    float dv = d_dinv[warp];
    float2 bb = ((const float2*)b2)[lane];
    __half2 zz = __floats2half2_rn(dv * acc.x + bb.x, dv * acc.y + bb.y);
    ((unsigned*)d_z)[(size_t)warp * 32 + lane] = *(unsigned*)&zz;
}

// ---------------- decoder: 4 lanes per edge, fp16 z, fp32 accumulate ---------
__global__ void k_decode(const int* __restrict__ pos32, const int* __restrict__ neg32,
                         float* __restrict__ out) {
    long long gt = (long long)blockIdx.x * blockDim.x + threadIdx.x;
    long long e = gt >> 2;
    int sub = threadIdx.x & 3;
    if (e >= 2LL * NE) return;
    const int* p;
    long long ee;
    float* o;
    if (e < NE) { p = pos32; ee = e; o = out; }
    else        { p = neg32; ee = e - NE; o = out + NE; }
    int flag = d_flag;
    int s = ld_idx(p, ee, flag);
    int d = ld_idx(p, NE + ee, flag);
    const uint4* z4 = (const uint4*)d_z;  // node row = 8 uint4 (64 halves)
    uint4 a0 = z4[(size_t)s * 8 + sub * 2];
    uint4 a1 = z4[(size_t)s * 8 + sub * 2 + 1];
    uint4 c0 = z4[(size_t)d * 8 + sub * 2];
    uint4 c1 = z4[(size_t)d * 8 + sub * 2 + 1];
    const __half2* ah0 = reinterpret_cast<const __half2*>(&a0);
    const __half2* ah1 = reinterpret_cast<const __half2*>(&a1);
    const __half2* ch0 = reinterpret_cast<const __half2*>(&c0);
    const __half2* ch1 = reinterpret_cast<const __half2*>(&c1);
    float pr = 0.f;
    #pragma unroll
    for (int i = 0; i < 4; i++) {
        float2 fa = __half22float2(ah0[i]);
        float2 fc = __half22float2(ch0[i]);
        pr += fa.x * fc.x + fa.y * fc.y;
        float2 ga = __half22float2(ah1[i]);
        float2 gc = __half22float2(ch1[i]);
        pr += ga.x * gc.x + ga.y * gc.y;
    }
    pr += __shfl_down_sync(0xffffffffu, pr, 2, 4);
    pr += __shfl_down_sync(0xffffffffu, pr, 1, 4);
    if (sub == 0) o[ee] = pr;
}

// ---------------- launch ------------------------------------------------------
extern "C" void kernel_launch(void* const* d_in, const int* in_sizes, int n_in,
                              void* d_out, int out_size) {
    const float* x     = (const float*)d_in[0];
    const int*   pos32 = (const int*)d_in[1];
    const int*   neg32 = (const int*)d_in[2];
    const float* W1    = (const float*)d_in[3];
    const float* b1    = (const float*)d_in[4];
    const float* W2    = (const float*)d_in[5];
    const float* b2    = (const float*)d_in[6];
    float* out = (float*)d_out;

    __half *xh, *g, *w1h, *w2h;
    int *degp, *syncp;
    cudaGetSymbolAddress((void**)&xh,    d_xh);
    cudaGetSymbolAddress((void**)&g,     d_g);
    cudaGetSymbolAddress((void**)&w1h,   d_w1h);
    cudaGetSymbolAddress((void**)&w2h,   d_w2h);
    cudaGetSymbolAddress((void**)&degp,  d_deg);
    cudaGetSymbolAddress((void**)&syncp, d_sync);

    const int smem1 = (64 * (128 + 8) + 128 * (128 + 8)) * (int)sizeof(__half);  // 52224
    const int smem2 = (64 * (128 + 8) + 128 * (64 + 8))  * (int)sizeof(__half);  // 35840
    cudaFuncSetAttribute(k_gemm_wmma<128>, cudaFuncAttributeMaxDynamicSharedMemorySize, smem1);
    cudaFuncSetAttribute(k_gemm_wmma<64>,  cudaFuncAttributeMaxDynamicSharedMemorySize, smem2);

    cudaStream_t cap = cudaStreamPerThread;
    cudaStream_t s2;
    cudaStreamCreate(&s2);
    cudaEvent_t e0, e_conv, e_scan, e_fill;
    cudaEventCreateWithFlags(&e0,     cudaEventDisableTiming);
    cudaEventCreateWithFlags(&e_conv, cudaEventDisableTiming);
    cudaEventCreateWithFlags(&e_scan, cudaEventDisableTiming);
    cudaEventCreateWithFlags(&e_fill, cudaEventDisableTiming);

    // side stream: x -> fp16 (DRAM-bound), overlaps fused CSR front
    cudaEventRecord(e0, cap);
    cudaStreamWaitEvent(s2, e0, 0);
    k_convx<<<(NN * 128 / 8 + 255) / 256, 256, 0, s2>>>(x);
    cudaEventRecord(e_conv, s2);

    // main: zero deg + sync counters, then fused front (convw+detect|degree|scan)
    cudaMemsetAsync(degp, 0, NN * sizeof(int), cap);
    cudaMemsetAsync(syncp, 0, 4 * sizeof(int), cap);
    k_front<<<FBLK, FTHR, 0, cap>>>(pos32, W1, W2);
    cudaEventRecord(e_scan, cap);

    // side: fill (atomic/L2-bound) overlaps GEMM1 (tensor-bound)
    cudaStreamWaitEvent(s2, e_scan, 0);
    k_fill<<<(NE + 255) / 256, 256, 0, s2>>>(pos32);
    cudaEventRecord(e_fill, s2);

    // main: GEMM1 g1 = dinv * (x @ W1) fp16
    cudaStreamWaitEvent(cap, e_conv, 0);
    k_gemm_wmma<128><<<(NN + 63) / 64, 256, smem1, cap>>>(xh, w1h, g);

    cudaStreamWaitEvent(cap, e_fill, 0);
    // h1 = relu(dinv*agg + b1) fp16 -> xh
    k_gather1<<<(NN * 32 + 255) / 256, 256, 0, cap>>>(b1);

    // GEMM2 + gather2
    k_gemm_wmma<64><<<(NN + 63) / 64, 128, smem2, cap>>>(xh, w2h, g);
    k_gather2<<<(NN * 32 + 255) / 256, 256, 0, cap>>>(b2);

    // decode
    long long tot = 2LL * NE * 4;
    k_decode<<<(unsigned)((tot + 255) / 256), 256, 0, cap>>>(pos32, neg32, out);

    cudaEventDestroy(e0);
    cudaEventDestroy(e_conv);
    cudaEventDestroy(e_scan);
    cudaEventDestroy(e_fill);
    cudaStreamDestroy(s2);
}

// round 15
// speedup vs baseline: 1.0842x; 1.0842x over previous
#include <cuda_runtime.h>
#include <cuda_fp16.h>
#include <mma.h>
#include <cstdint>

using namespace nvcuda;

#define NN   100000
#define NE   1600000

// ---------------- scratch (device globals; no allocation allowed) ----------
__device__ int    d_flag;                // 1 => edge indices stored as int64
__device__ int    d_deg[NN];             // in-degree incl self loop
__device__ float  d_dinv[NN];            // deg^-1/2
__device__ int    d_off[NN + 1];         // CSR offsets (by dst)
__device__ int    d_cur[NN];             // fill cursors
__device__ int    d_bsum[128];           // per-block scan totals
__device__ int    d_scnt;                // scan publish counter (reset in k_pre)
__device__ int    d_srcl[NE];            // CSR src lists
__device__ __half d_xh[(size_t)NN * 128];  // x fp16, later h1 fp16
__device__ __half d_g[(size_t)NN * 128];   // g1 fp16 (128w) / g2 fp16 (64w)
__device__ __half d_z[(size_t)NN * 64];    // z fp16
__device__ __half d_w1h[128 * 128];
__device__ __half d_w2h[128 * 64];

__device__ __forceinline__ int ld_idx(const int* __restrict__ p, long long i, int flag) {
    return flag ? p[2 * i] : p[i];
}

// ---------------- fused: init_deg + weight conversion + index detect ---------
__global__ void k_pre(const int* __restrict__ p,
                      const float* __restrict__ W1, const float* __restrict__ W2) {
    int i = blockIdx.x * blockDim.x + threadIdx.x;
    if (i == 0) d_scnt = 0;                         // reset scan handshake
    if (i < NN) d_deg[i] = 1;                       // self loop
    if (i < 128 * 128) d_w1h[i] = __float2half(W1[i]);
    if (i < 128 * 64)  d_w2h[i] = __float2half(W2[i]);
    if (blockIdx.x == 0 && threadIdx.x < 32) {
        int nz = 0;
        for (int j = threadIdx.x; j < 512; j += 32) nz |= p[2 * j + 1];
        for (int o = 16; o; o >>= 1) nz |= __shfl_down_sync(0xffffffffu, nz, o);
        if (threadIdx.x == 0) d_flag = (nz == 0) ? 1 : 0;
    }
}

// ---------------- x -> fp16 ---------------------------------------------------
__global__ void k_convx(const float* __restrict__ x) {
    long long i = (long long)blockIdx.x * blockDim.x + threadIdx.x;  // 8-half unit
    if (i >= (long long)NN * 128 / 8) return;
    float4 a = *(const float4*)&x[i * 8];
    float4 b = *(const float4*)&x[i * 8 + 4];
    __half2 h[4];
    h[0] = __floats2half2_rn(a.x, a.y);
    h[1] = __floats2half2_rn(a.z, a.w);
    h[2] = __floats2half2_rn(b.x, b.y);
    h[3] = __floats2half2_rn(b.z, b.w);
    *(uint4*)&d_xh[i * 8] = *(uint4*)h;
}

// ---------------- degree ------------------------------------------------------
__global__ void k_degree(const int* __restrict__ p) {
    long long e = (long long)blockIdx.x * blockDim.x + threadIdx.x;
    if (e >= NE) return;
    int flag = d_flag;
    int dst = ld_idx(p, NE + e, flag);
    atomicAdd(&d_deg[dst], 1);
}

// ---------------- single-launch scan (R12-proven) ------------------------------
__global__ void k_scanf() {
    __shared__ int wsum[32];
    __shared__ int sh[128];
    __shared__ int ws2[4];
    int tid = threadIdx.x, lane = tid & 31, wid = tid >> 5;
    int v = blockIdx.x * 1024 + tid;
    int deg = (v < NN) ? d_deg[v] : 1;
    if (v < NN) d_dinv[v] = rsqrtf((float)deg);
    int val = (v < NN) ? (deg - 1) : 0;
    int x = val;
    #pragma unroll
    for (int o = 1; o < 32; o <<= 1) {
        int t = __shfl_up_sync(0xffffffffu, x, o);
        if (lane >= o) x += t;
    }
    if (lane == 31) wsum[wid] = x;
    __syncthreads();
    if (wid == 0) {
        int y = wsum[lane];
        #pragma unroll
        for (int o = 1; o < 32; o <<= 1) {
            int t = __shfl_up_sync(0xffffffffu, y, o);
            if (lane >= o) y += t;
        }
        wsum[lane] = y;
    }
    __syncthreads();
    int warpoff = wid ? wsum[wid - 1] : 0;
    int excl = warpoff + x - val;     // block-local exclusive prefix

    if (tid == 0) {
        d_bsum[blockIdx.x] = wsum[31];
        __threadfence();
        atomicAdd(&d_scnt, 1);
        while (*(volatile int*)&d_scnt < (int)gridDim.x) __nanosleep(32);
        __threadfence();
    }
    __syncthreads();

    int bx = 0;
    if (tid < 128) {
        int bval = (tid < (int)gridDim.x) ? *(volatile int*)&d_bsum[tid] : 0;
        bx = bval;
        #pragma unroll
        for (int o = 1; o < 32; o <<= 1) {
            int t = __shfl_up_sync(0xffffffffu, bx, o);
            if (lane >= o) bx += t;
        }
        if (lane == 31) ws2[wid] = bx;
    }
    __syncthreads();
    if (tid < 128) {
        int add2 = 0;
        for (int q = 0; q < wid; q++) add2 += ws2[q];
        sh[tid] = bx + add2;
    }
    __syncthreads();

    int addb = blockIdx.x ? sh[blockIdx.x - 1] : 0;
    if (v < NN) {
        int o = excl + addb;
        d_off[v] = o;
        d_cur[v] = o;
    }
    if (v == 0) d_off[NN] = NE;
}

// ---------------- CSR fill ---------------------------------------------------
__global__ void k_fill(const int* __restrict__ p) {
    long long e = (long long)blockIdx.x * blockDim.x + threadIdx.x;
    if (e >= NE) return;
    int flag = d_flag;
    int src = ld_idx(p, e, flag);
    int dst = ld_idx(p, NE + e, flag);
    int pos = atomicAdd(&d_cur[dst], 1);
    d_srcl[pos] = src;
}

// ---------------- wmma GEMM, 32x64 register tile per warp ---------------------
// BM=128 rows/block. Warp computes 2 M-frags x 4 N-frags -> fragment loads
// per MMA drop from 1.25 to 0.75. NWM = BM/32, NWN = BN/64.
template <int BN>
__global__ void k_gemm_wmma(const __half* __restrict__ A, const __half* __restrict__ Wh,
                            __half* __restrict__ out) {
    constexpr int BM = 128, K = 128;
    constexpr int LDA = K + 8;
    constexpr int LDW = BN + 8;
    constexpr int NWM = BM / 32;           // 4
    constexpr int NWN = BN / 64;           // 2 or 1
    constexpr int NWARP = NWM * NWN;       // 8 or 4
    constexpr int NT = NWARP * 32;
    extern __shared__ __half dyn[];
    __half* sA = dyn;                   // BM * LDA
    __half* sW = dyn + BM * LDA;        // K * LDW

    const int tid = threadIdx.x;
    const int wid = tid >> 5, lane = tid & 31;
    const int wm = wid % NWM, wn = wid / NWM;
    const int rowBase = blockIdx.x * BM;

    for (int i = tid; i < BM * K / 8; i += NT) {
        int r = i >> 4;
        int c = (i & 15) * 8;
        int row = min(rowBase + r, NN - 1);
        *(uint4*)&sA[r * LDA + c] = *(const uint4*)&A[(size_t)row * K + c];
    }
    for (int i = tid; i < K * BN / 8; i += NT) {
        int r = i / (BN / 8);
        int c = (i % (BN / 8)) * 8;
        *(uint4*)&sW[r * LDW + c] = *(const uint4*)&Wh[(size_t)r * BN + c];
    }
    __syncthreads();

    wmma::fragment<wmma::accumulator, 16, 16, 16, float> c[2][4];
    #pragma unroll
    for (int mt = 0; mt < 2; mt++)
        #pragma unroll
        for (int n = 0; n < 4; n++) wmma::fill_fragment(c[mt][n], 0.f);

    #pragma unroll
    for (int k = 0; k < K; k += 16) {
        wmma::fragment<wmma::matrix_a, 16, 16, 16, __half, wmma::row_major> a[2];
        #pragma unroll
        for (int mt = 0; mt < 2; mt++)
            wmma::load_matrix_sync(a[mt], &sA[(wm * 32 + mt * 16) * LDA + k], LDA);
        #pragma unroll
        for (int n = 0; n < 4; n++) {
            wmma::fragment<wmma::matrix_b, 16, 16, 16, __half, wmma::row_major> b;
            wmma::load_matrix_sync(b, &sW[k * LDW + wn * 64 + n * 16], LDW);
            #pragma unroll
            for (int mt = 0; mt < 2; mt++)
                wmma::mma_sync(c[mt][n], a[mt], b, c[mt][n]);
        }
    }
    __syncthreads();  // done with sW; reuse as fp32 staging (16x64 f32 per warp)

    float* stage = (float*)sW + (size_t)wid * 16 * 64;  // 4KB per warp
    #pragma unroll
    for (int mt = 0; mt < 2; mt++) {
        #pragma unroll
        for (int n = 0; n < 4; n++)
            wmma::store_matrix_sync(stage + n * 16, c[mt][n], 64, wmma::mem_row_major);
        __syncwarp();
        for (int i = lane; i < 128; i += 32) {
            int r = i >> 3;
            int cc = (i & 7) * 8;
            int row = rowBase + wm * 32 + mt * 16 + r;
            if (row < NN) {
                float dv = d_dinv[row];
                __half2 hv[4];
                #pragma unroll
                for (int q = 0; q < 4; q++) {
                    float v0 = stage[r * 64 + cc + 2 * q] * dv;
                    float v1 = stage[r * 64 + cc + 2 * q + 1] * dv;
                    hv[q] = __floats2half2_rn(v0, v1);
                }
                *(uint4*)&out[(size_t)row * BN + wn * 64 + cc] = *(uint4*)hv;
            }
        }
        __syncwarp();
    }
}

// ---------------- layer-1 aggregate: warp per node, 128 cols fp16 ------------
__global__ void k_gather1(const float* __restrict__ b1) {
    int warp = (blockIdx.x * blockDim.x + threadIdx.x) >> 5;
    int lane = threadIdx.x & 31;
    if (warp >= NN) return;
    const uint2* g = (const uint2*)d_g;
    uint2 sv = g[(size_t)warp * 32 + lane];
    float2 f0 = __half22float2(*(__half2*)&sv.x);
    float2 f1 = __half22float2(*(__half2*)&sv.y);
    float4 acc = make_float4(f0.x, f0.y, f1.x, f1.y);  // self-loop term
    int s = d_off[warp], e = d_off[warp + 1];
    for (int i = s; i < e; i += 32) {
        int u = (i + lane < e) ? d_srcl[i + lane] : 0;
        int m = min(32, e - i);
        for (int j = 0; j < m; j++) {
            int uu = __shfl_sync(0xffffffffu, u, j);
            uint2 tv = g[(size_t)uu * 32 + lane];
            float2 t0 = __half22float2(*(__half2*)&tv.x);
            float2 t1 = __half22float2(*(__half2*)&tv.y);
            acc.x += t0.x; acc.y += t0.y; acc.z += t1.x; acc.w += t1.y;
        }
    }
    float dv = d_dinv[warp];
    float4 bb = ((const float4*)b1)[lane];
    __half2 h0 = __floats2half2_rn(fmaxf(dv * acc.x + bb.x, 0.f),
                                   fmaxf(dv * acc.y + bb.y, 0.f));
    __half2 h1 = __floats2half2_rn(fmaxf(dv * acc.z + bb.z, 0.f),
                                   fmaxf(dv * acc.w + bb.w, 0.f));
    uint2 o;
    o.x = *(unsigned*)&h0;
    o.y = *(unsigned*)&h1;
    ((uint2*)d_xh)[(size_t)warp * 32 + lane] = o;  // h1 fp16 over xh
}

// ---------------- layer-2 aggregate: warp per node, 64 cols fp16 -------------
__global__ void k_gather2(const float* __restrict__ b2) {
    int warp = (blockIdx.x * blockDim.x + threadIdx.x) >> 5;
    int lane = threadIdx.x & 31;
    if (warp >= NN) return;
    const unsigned* g = (const unsigned*)d_g;
    float2 acc = __half22float2(*(__half2*)&g[(size_t)warp * 32 + lane]);
    int s = d_off[warp], e = d_off[warp + 1];
    for (int i = s; i < e; i += 32) {
        int u = (i + lane < e) ? d_srcl[i + lane] : 0;
        int m = min(32, e - i);
        for (int j = 0; j < m; j++) {
            int uu = __shfl_sync(0xffffffffu, u, j);
            unsigned tv = g[(size_t)uu * 32 + lane];
            float2 t = __half22float2(*(__half2*)&tv);
            acc.x += t.x; acc.y += t.y;
        }
    }
    float dv = d_dinv[warp];
    float2 bb = ((const float2*)b2)[lane];
    __half2 zz = __floats2half2_rn(dv * acc.x + bb.x, dv * acc.y + bb.y);
    ((unsigned*)d_z)[(size_t)warp * 32 + lane] = *(unsigned*)&zz;
}

// ---------------- decoder: 4 lanes per edge, fp16 z, fp32 accumulate ---------
__global__ void k_decode(const int* __restrict__ pos32, const int* __restrict__ neg32,
                         float* __restrict__ out) {
    long long gt = (long long)blockIdx.x * blockDim.x + threadIdx.x;
    long long e = gt >> 2;
    int sub = threadIdx.x & 3;
    if (e >= 2LL * NE) return;
    const int* p;
    long long ee;
    float* o;
    if (e < NE) { p = pos32; ee = e; o = out; }
    else        { p = neg32; ee = e - NE; o = out + NE; }
    int flag = d_flag;
    int s = ld_idx(p, ee, flag);
    int d = ld_idx(p, NE + ee, flag);
    const uint4* z4 = (const uint4*)d_z;  // node row = 8 uint4 (64 halves)
    uint4 a0 = z4[(size_t)s * 8 + sub * 2];
    uint4 a1 = z4[(size_t)s * 8 + sub * 2 + 1];
    uint4 c0 = z4[(size_t)d * 8 + sub * 2];
    uint4 c1 = z4[(size_t)d * 8 + sub * 2 + 1];
    const __half2* ah0 = reinterpret_cast<const __half2*>(&a0);
    const __half2* ah1 = reinterpret_cast<const __half2*>(&a1);
    const __half2* ch0 = reinterpret_cast<const __half2*>(&c0);
    const __half2* ch1 = reinterpret_cast<const __half2*>(&c1);
    float pr = 0.f;
    #pragma unroll
    for (int i = 0; i < 4; i++) {
        float2 fa = __half22float2(ah0[i]);
        float2 fc = __half22float2(ch0[i]);
        pr += fa.x * fc.x + fa.y * fc.y;
        float2 ga = __half22float2(ah1[i]);
        float2 gc = __half22float2(ch1[i]);
        pr += ga.x * gc.x + ga.y * gc.y;
    }
    pr += __shfl_down_sync(0xffffffffu, pr, 2, 4);
    pr += __shfl_down_sync(0xffffffffu, pr, 1, 4);
    if (sub == 0) o[ee] = pr;
}

// ---------------- launch ------------------------------------------------------
extern "C" void kernel_launch(void* const* d_in, const int* in_sizes, int n_in,
                              void* d_out, int out_size) {
    const float* x     = (const float*)d_in[0];
    const int*   pos32 = (const int*)d_in[1];
    const int*   neg32 = (const int*)d_in[2];
    const float* W1    = (const float*)d_in[3];
    const float* b1    = (const float*)d_in[4];
    const float* W2    = (const float*)d_in[5];
    const float* b2    = (const float*)d_in[6];
    float* out = (float*)d_out;

    __half *xh, *g, *w1h, *w2h;
    cudaGetSymbolAddress((void**)&xh,  d_xh);
    cudaGetSymbolAddress((void**)&g,   d_g);
    cudaGetSymbolAddress((void**)&w1h, d_w1h);
    cudaGetSymbolAddress((void**)&w2h, d_w2h);

    const int smem1 = (128 * (128 + 8) + 128 * (128 + 8)) * (int)sizeof(__half);  // 69632
    const int smem2 = (128 * (128 + 8) + 128 * (64 + 8))  * (int)sizeof(__half);  // 53248
    cudaFuncSetAttribute(k_gemm_wmma<128>, cudaFuncAttributeMaxDynamicSharedMemorySize, smem1);
    cudaFuncSetAttribute(k_gemm_wmma<64>,  cudaFuncAttributeMaxDynamicSharedMemorySize, smem2);

    const int nscan = (NN + 1023) / 1024;  // 98 (< 148 SMs: co-resident)

    cudaStream_t cap = cudaStreamPerThread;
    cudaStream_t s2;
    cudaStreamCreate(&s2);
    cudaEvent_t e0, e_conv, e_scan, e_fill;
    cudaEventCreateWithFlags(&e0,     cudaEventDisableTiming);
    cudaEventCreateWithFlags(&e_conv, cudaEventDisableTiming);
    cudaEventCreateWithFlags(&e_scan, cudaEventDisableTiming);
    cudaEventCreateWithFlags(&e_fill, cudaEventDisableTiming);

    // side stream: x -> fp16 (DRAM-bound), overlaps CSR chain
    cudaEventRecord(e0, cap);
    cudaStreamWaitEvent(s2, e0, 0);
    k_convx<<<(NN * 128 / 8 + 255) / 256, 256, 0, s2>>>(x);
    cudaEventRecord(e_conv, s2);

    // main: fused pre (init_deg + convw + detect + scnt reset) -> degree -> scan
    k_pre<<<(NN + 255) / 256, 256, 0, cap>>>(pos32, W1, W2);
    k_degree<<<(NE + 255) / 256, 256, 0, cap>>>(pos32);
    k_scanf<<<nscan, 1024, 0, cap>>>();
    cudaEventRecord(e_scan, cap);

    // side: fill (atomic/L2-bound) overlaps GEMM1 (tensor-bound)
    cudaStreamWaitEvent(s2, e_scan, 0);
    k_fill<<<(NE + 255) / 256, 256, 0, s2>>>(pos32);
    cudaEventRecord(e_fill, s2);

    // main: GEMM1 g1 = dinv * (x @ W1) fp16   (BM=128, 8 warps)
    cudaStreamWaitEvent(cap, e_conv, 0);
    k_gemm_wmma<128><<<(NN + 127) / 128, 256, smem1, cap>>>(xh, w1h, g);

    cudaStreamWaitEvent(cap, e_fill, 0);
    // h1 = relu(dinv*agg + b1) fp16 -> xh
    k_gather1<<<(NN * 32 + 255) / 256, 256, 0, cap>>>(b1);

    // GEMM2 (BM=128, 4 warps) + gather2
    k_gemm_wmma<64><<<(NN + 127) / 128, 128, smem2, cap>>>(xh, w2h, g);
    k_gather2<<<(NN * 32 + 255) / 256, 256, 0, cap>>>(b2);

    // decode
    long long tot = 2LL * NE * 4;
    k_decode<<<(unsigned)((tot + 255) / 256), 256, 0, cap>>>(pos32, neg32, out);

    cudaEventDestroy(e0);
    cudaEventDestroy(e_conv);
    cudaEventDestroy(e_scan);
    cudaEventDestroy(e_fill);
    cudaStreamDestroy(s2);
}